// round 1
// baseline (speedup 1.0000x reference)
#include <cuda_runtime.h>

#define N_NODES 50000
#define N_EDGES 800000
#define ET (N_EDGES + N_NODES)   // self-loops appended
#define N_GRAPHS 64

// ---------------- scratch (device globals; no allocations) ----------------
__device__ __align__(16) float g_xl1[N_NODES * 128];
__device__ __align__(16) float g_xr1[N_NODES * 128];
__device__ __align__(16) float g_h  [N_NODES * 128];
__device__ __align__(16) float g_ea1[(size_t)ET * 2];
__device__ float g_denom1[N_NODES * 2];
__device__ __align__(16) float g_xl2[N_NODES * 3];
__device__ __align__(16) float g_xr2[N_NODES * 3];
__device__ float g_ea2[ET];
__device__ float g_denom2[N_NODES];
__device__ float g_out2[N_NODES * 3];
__device__ float g_pool[N_GRAPHS * 4];

__device__ __forceinline__ float lrelu(float v) { return v > 0.f ? v : 0.2f * v; }

// ---------------- init: biases into accumulators, zeros elsewhere ----------
__global__ void init_kernel(const float* __restrict__ b1, const float* __restrict__ b2) {
    int i = blockIdx.x * blockDim.x + threadIdx.x;
    if (i < N_NODES * 128) g_h[i] = b1[i & 127];
    if (i < N_NODES * 3)   g_out2[i] = b2[i % 3];
    if (i < N_NODES * 2)   g_denom1[i] = 0.f;
    if (i < N_NODES)       g_denom2[i] = 0.f;
    if (i < N_GRAPHS * 4)  g_pool[i] = 0.f;
}

// ---------------- GEMM1: xl1 = x@W1l, xr1 = x@W1r (fused, N=256) -----------
// block: 256 threads, tile 32 rows x 256 cols; thread owns 4 cols x 8 rows
__global__ void gemm1_kernel(const float* __restrict__ x,
                             const float* __restrict__ Wl,
                             const float* __restrict__ Wr) {
    __shared__ float xs[32][128];
    int row0 = blockIdx.x * 32;
    float4* xsv = (float4*)&xs[0][0];
    for (int i = threadIdx.x; i < 32 * 32; i += 256) {
        int r = row0 + (i >> 5);
        float4 v = make_float4(0.f, 0.f, 0.f, 0.f);
        if (r < N_NODES) v = ((const float4*)x)[(size_t)r * 32 + (i & 31)];
        xsv[i] = v;
    }
    __syncthreads();

    int tx = threadIdx.x & 63;   // base col (cols tx, tx+64, tx+128, tx+192)
    int ty = threadIdx.x >> 6;   // row group: rows ty*8 .. ty*8+7

    float acc[4][8];
#pragma unroll
    for (int c = 0; c < 4; c++)
#pragma unroll
        for (int r = 0; r < 8; r++) acc[c][r] = 0.f;

#pragma unroll 4
    for (int k = 0; k < 128; k++) {
        float w[4];
        // cols 0..127 -> Wl, 128..255 -> Wr (resolved at compile time per c)
        w[0] = Wl[k * 128 + tx];
        w[1] = Wl[k * 128 + tx + 64];
        w[2] = Wr[k * 128 + tx];
        w[3] = Wr[k * 128 + tx + 64];
#pragma unroll
        for (int r = 0; r < 8; r++) {
            float xv = xs[ty * 8 + r][k];
#pragma unroll
            for (int c = 0; c < 4; c++) acc[c][r] += xv * w[c];
        }
    }

#pragma unroll
    for (int r = 0; r < 8; r++) {
        int row = row0 + ty * 8 + r;
        if (row >= N_NODES) continue;
        g_xl1[(size_t)row * 128 + tx]       = acc[0][r];
        g_xl1[(size_t)row * 128 + tx + 64]  = acc[1][r];
        g_xr1[(size_t)row * 128 + tx]       = acc[2][r];
        g_xr1[(size_t)row * 128 + tx + 64]  = acc[3][r];
    }
}

// ---------------- layer1 attention: warp per edge ---------------------------
// lanes 0-15 -> head 0 (ch 0..63), lanes 16-31 -> head 1 (ch 64..127)
__global__ void l1_att_kernel(const int* __restrict__ ei,
                              const float* __restrict__ att1) {
    int gid = blockIdx.x * blockDim.x + threadIdx.x;
    int e = gid >> 5;
    if (e >= ET) return;
    int lane = threadIdx.x & 31;
    int src, dst;
    if (e < N_EDGES) { src = ei[e]; dst = ei[N_EDGES + e]; }
    else             { src = dst = e - N_EDGES; }
    int c0 = lane * 4;
    float4 a  = *(const float4*)(g_xl1 + (size_t)src * 128 + c0);
    float4 b  = *(const float4*)(g_xr1 + (size_t)dst * 128 + c0);
    float4 at = *(const float4*)(att1 + c0);   // att1 is [2,64] contiguous
    float p = at.x * lrelu(a.x + b.x) + at.y * lrelu(a.y + b.y)
            + at.z * lrelu(a.z + b.z) + at.w * lrelu(a.w + b.w);
    // reduce within each 16-lane half
    p += __shfl_xor_sync(0xffffffffu, p, 8, 16);
    p += __shfl_xor_sync(0xffffffffu, p, 4, 16);
    p += __shfl_xor_sync(0xffffffffu, p, 2, 16);
    p += __shfl_xor_sync(0xffffffffu, p, 1, 16);
    if ((lane & 15) == 0) {
        int h = lane >> 4;
        float ea = __expf(p);   // alpha is small; no max-subtraction needed
        g_ea1[(size_t)e * 2 + h] = ea;
        atomicAdd(&g_denom1[dst * 2 + h], ea);
    }
}

// ---------------- layer1 aggregate: warp per edge, atomic scatter -----------
__global__ void l1_agg_kernel(const int* __restrict__ ei) {
    int gid = blockIdx.x * blockDim.x + threadIdx.x;
    int e = gid >> 5;
    if (e >= ET) return;
    int lane = threadIdx.x & 31;
    int src, dst;
    if (e < N_EDGES) { src = ei[e]; dst = ei[N_EDGES + e]; }
    else             { src = dst = e - N_EDGES; }
    int h = lane >> 4;
    float ea = g_ea1[(size_t)e * 2 + h];
    float w  = ea / (g_denom1[dst * 2 + h] + 1e-16f);
    int c0 = lane * 4;
    float4 a = *(const float4*)(g_xl1 + (size_t)src * 128 + c0);
    float* o = g_h + (size_t)dst * 128 + c0;
    atomicAdd(o + 0, a.x * w);
    atomicAdd(o + 1, a.y * w);
    atomicAdd(o + 2, a.z * w);
    atomicAdd(o + 3, a.w * w);
}

// ---------------- ELU ------------------------------------------------------
__global__ void elu_kernel() {
    int i = blockIdx.x * blockDim.x + threadIdx.x;
    if (i < N_NODES * 128) {
        float v = g_h[i];
        g_h[i] = v > 0.f ? v : (__expf(v) - 1.f);
    }
}

// ---------------- GEMM2: xl2 = h@W2l, xr2 = h@W2r  (K=128, N=3) -------------
__global__ void gemm2_kernel(const float* __restrict__ W2l,
                             const float* __restrict__ W2r) {
    int gid = blockIdx.x * blockDim.x + threadIdx.x;
    int row = gid >> 5;
    if (row >= N_NODES) return;
    int lane = threadIdx.x & 31;
    float4 hv = *(const float4*)(g_h + (size_t)row * 128 + lane * 4);
    float v[4] = {hv.x, hv.y, hv.z, hv.w};
    float pl[3] = {0.f, 0.f, 0.f};
    float pr[3] = {0.f, 0.f, 0.f};
#pragma unroll
    for (int j = 0; j < 4; j++) {
        int k = lane * 4 + j;
#pragma unroll
        for (int c = 0; c < 3; c++) {
            pl[c] += v[j] * W2l[k * 3 + c];
            pr[c] += v[j] * W2r[k * 3 + c];
        }
    }
#pragma unroll
    for (int o = 16; o >= 1; o >>= 1) {
#pragma unroll
        for (int c = 0; c < 3; c++) {
            pl[c] += __shfl_xor_sync(0xffffffffu, pl[c], o);
            pr[c] += __shfl_xor_sync(0xffffffffu, pr[c], o);
        }
    }
    if (lane == 0) {
#pragma unroll
        for (int c = 0; c < 3; c++) {
            g_xl2[row * 3 + c] = pl[c];
            g_xr2[row * 3 + c] = pr[c];
        }
    }
}

// ---------------- layer2 attention: thread per edge -------------------------
__global__ void l2_att_kernel(const int* __restrict__ ei,
                              const float* __restrict__ att2) {
    int e = blockIdx.x * blockDim.x + threadIdx.x;
    if (e >= ET) return;
    int src, dst;
    if (e < N_EDGES) { src = ei[e]; dst = ei[N_EDGES + e]; }
    else             { src = dst = e - N_EDGES; }
    float p = att2[0] * lrelu(g_xl2[src * 3 + 0] + g_xr2[dst * 3 + 0])
            + att2[1] * lrelu(g_xl2[src * 3 + 1] + g_xr2[dst * 3 + 1])
            + att2[2] * lrelu(g_xl2[src * 3 + 2] + g_xr2[dst * 3 + 2]);
    float ea = __expf(p);
    g_ea2[e] = ea;
    atomicAdd(&g_denom2[dst], ea);
}

// ---------------- layer2 aggregate ------------------------------------------
__global__ void l2_agg_kernel(const int* __restrict__ ei) {
    int e = blockIdx.x * blockDim.x + threadIdx.x;
    if (e >= ET) return;
    int src, dst;
    if (e < N_EDGES) { src = ei[e]; dst = ei[N_EDGES + e]; }
    else             { src = dst = e - N_EDGES; }
    float w = g_ea2[e] / (g_denom2[dst] + 1e-16f);
    atomicAdd(&g_out2[dst * 3 + 0], g_xl2[src * 3 + 0] * w);
    atomicAdd(&g_out2[dst * 3 + 1], g_xl2[src * 3 + 1] * w);
    atomicAdd(&g_out2[dst * 3 + 2], g_xl2[src * 3 + 2] * w);
}

// ---------------- global mean pool (batch is sorted) ------------------------
__global__ void pool_kernel(const int* __restrict__ batch) {
    __shared__ float sb[N_GRAPHS * 4];
    for (int i = threadIdx.x; i < N_GRAPHS * 4; i += blockDim.x) sb[i] = 0.f;
    __syncthreads();
    int n = blockIdx.x * blockDim.x + threadIdx.x;
    if (n < N_NODES) {
        int g = batch[n];
        atomicAdd(&sb[g * 4 + 0], g_out2[n * 3 + 0]);
        atomicAdd(&sb[g * 4 + 1], g_out2[n * 3 + 1]);
        atomicAdd(&sb[g * 4 + 2], g_out2[n * 3 + 2]);
        atomicAdd(&sb[g * 4 + 3], 1.f);
    }
    __syncthreads();
    for (int i = threadIdx.x; i < N_GRAPHS * 4; i += blockDim.x)
        atomicAdd(&g_pool[i], sb[i]);
}

// ---------------- final MLP: thread per graph -------------------------------
__global__ void mlp_kernel(const float* __restrict__ Wr1, const float* __restrict__ br1,
                           const float* __restrict__ Wr2, const float* __restrict__ br2,
                           float* __restrict__ out) {
    int g = threadIdx.x;
    if (g >= N_GRAPHS) return;
    float cnt = g_pool[g * 4 + 3];
    float inv = 1.f / fmaxf(cnt, 1.f);
    float v0 = g_pool[g * 4 + 0] * inv;
    float v1 = g_pool[g * 4 + 1] * inv;
    float v2 = g_pool[g * 4 + 2] * inv;
    float o0 = br2[0], o1 = br2[1], o2 = br2[2];
#pragma unroll 8
    for (int j = 0; j < 64; j++) {
        // Wr1 is (3,64): Wr1[c*64+j]
        float hj = v0 * Wr1[j] + v1 * Wr1[64 + j] + v2 * Wr1[128 + j] + br1[j];
        hj = fmaxf(hj, 0.f);
        o0 += hj * Wr2[j * 3 + 0];
        o1 += hj * Wr2[j * 3 + 1];
        o2 += hj * Wr2[j * 3 + 2];
    }
    out[g * 3 + 0] = o0;
    out[g * 3 + 1] = o1;
    out[g * 3 + 2] = o2;
}

// ---------------- launch ----------------------------------------------------
extern "C" void kernel_launch(void* const* d_in, const int* in_sizes, int n_in,
                              void* d_out, int out_size) {
    (void)in_sizes; (void)n_in; (void)out_size;
    const float* x    = (const float*)d_in[0];
    const int*   ei   = (const int*)  d_in[1];
    const int*   batch= (const int*)  d_in[2];
    const float* W1l  = (const float*)d_in[3];
    const float* W1r  = (const float*)d_in[4];
    const float* att1 = (const float*)d_in[5];
    const float* b1   = (const float*)d_in[6];
    const float* W2l  = (const float*)d_in[7];
    const float* W2r  = (const float*)d_in[8];
    const float* att2 = (const float*)d_in[9];
    const float* b2   = (const float*)d_in[10];
    const float* Wr1  = (const float*)d_in[11];
    const float* br1  = (const float*)d_in[12];
    const float* Wr2  = (const float*)d_in[13];
    const float* br2  = (const float*)d_in[14];
    float* out = (float*)d_out;

    init_kernel<<<(N_NODES * 128 + 255) / 256, 256>>>(b1, b2);
    gemm1_kernel<<<(N_NODES + 31) / 32, 256>>>(x, W1l, W1r);
    {
        long long t = (long long)ET * 32;
        l1_att_kernel<<<(unsigned)((t + 255) / 256), 256>>>(ei, att1);
        l1_agg_kernel<<<(unsigned)((t + 255) / 256), 256>>>(ei);
    }
    elu_kernel<<<(N_NODES * 128 + 255) / 256, 256>>>();
    {
        long long t = (long long)N_NODES * 32;
        gemm2_kernel<<<(unsigned)((t + 255) / 256), 256>>>(W2l, W2r);
    }
    l2_att_kernel<<<(ET + 255) / 256, 256>>>(ei, att2);
    l2_agg_kernel<<<(ET + 255) / 256, 256>>>(ei);
    pool_kernel<<<(N_NODES + 255) / 256, 256>>>(batch);
    mlp_kernel<<<1, 64>>>(Wr1, br1, Wr2, br2, out);
}

// round 4
// speedup vs baseline: 1.5043x; 1.5043x over previous
#include <cuda_runtime.h>

#define N_NODES 50000
#define N_EDGES 800000
#define ET (N_EDGES + N_NODES)   // self-loops appended
#define N_GRAPHS 64
#define FULL 0xffffffffu

// ---------------- scratch (device globals; no allocations) ----------------
__device__ __align__(16) float g_xl1[N_NODES * 128];
__device__ __align__(16) float g_xr1[N_NODES * 128];
__device__ __align__(16) float g_h  [N_NODES * 128];
__device__ __align__(16) float g_xl2[N_NODES * 4];
__device__ __align__(16) float g_xr2[N_NODES * 4];
__device__ int g_cnt[N_NODES];
__device__ int g_rowptr[N_NODES + 1];
__device__ int g_cursor[N_NODES];
__device__ int g_csr_src[ET];
__device__ float g_pool[N_GRAPHS * 4];

__device__ __forceinline__ float lrelu(float v) { return v > 0.f ? v : 0.2f * v; }

// f32x2 packed FMA (sm_100+): d = a*b + d, elementwise on packed pairs
#define FMA2(d, a, b) asm("fma.rn.f32x2 %0, %1, %2, %0;" : "+l"(d) : "l"(a), "l"(b))
__device__ __forceinline__ unsigned long long pack2(float lo, float hi) {
    unsigned long long r;
    asm("mov.b64 %0, {%1, %2};" : "=l"(r) : "f"(lo), "f"(hi));
    return r;
}
__device__ __forceinline__ void unpack2(unsigned long long v, float& lo, float& hi) {
    asm("mov.b64 {%0, %1}, %2;" : "=f"(lo), "=f"(hi) : "l"(v));
}

// ---------------- init: zero CSR counters + pool ---------------------------
__global__ void init_kernel() {
    int i = blockIdx.x * blockDim.x + threadIdx.x;
    if (i < N_NODES) g_cnt[i] = 0;
    if (i < N_GRAPHS * 4) g_pool[i] = 0.f;
}

// ---------------- CSR: count incoming edges per dst (+ per-graph node cnt) -
__global__ void csr_count_kernel(const int* __restrict__ ei,
                                 const int* __restrict__ batch) {
    int e = blockIdx.x * blockDim.x + threadIdx.x;
    if (e < ET) {
        int dst = (e < N_EDGES) ? ei[N_EDGES + e] : (e - N_EDGES);
        atomicAdd(&g_cnt[dst], 1);
    }
    if (e < N_NODES) atomicAdd(&g_pool[batch[e] * 4 + 3], 1.f);
}

// ---------------- CSR: exclusive scan (single block, 1024 threads) ---------
__global__ void scan_kernel() {
    const int T = 1024;
    const int CH = (N_NODES + T - 1) / T;   // 49
    int t = threadIdx.x;
    int s0 = t * CH;
    int s1 = min(s0 + CH, N_NODES);
    int s = 0;
    for (int i = s0; i < s1; i++) s += g_cnt[i];
    __shared__ int sh[T];
    sh[t] = s;
    __syncthreads();
    for (int off = 1; off < T; off <<= 1) {
        int v = (t >= off) ? sh[t - off] : 0;
        __syncthreads();
        sh[t] += v;
        __syncthreads();
    }
    int run = (t == 0) ? 0 : sh[t - 1];
    for (int i = s0; i < s1; i++) {
        g_rowptr[i] = run;
        g_cursor[i] = run;
        run += g_cnt[i];
    }
    if (t == T - 1) g_rowptr[N_NODES] = ET;
}

// ---------------- CSR: scatter src ids into slots --------------------------
__global__ void csr_fill_kernel(const int* __restrict__ ei) {
    int e = blockIdx.x * blockDim.x + threadIdx.x;
    if (e >= ET) return;
    int src, dst;
    if (e < N_EDGES) { src = ei[e]; dst = ei[N_EDGES + e]; }
    else             { src = dst = e - N_EDGES; }
    int pos = atomicAdd(&g_cursor[dst], 1);
    g_csr_src[pos] = src;
}

// ---------------- GEMM1: xl1 = x@W1l, xr1 = x@W1r (f32x2 packed FMA) -------
// block: 256 threads, tile 32 rows x 256 cols; thread: 4 cols x 8 rows (4 row-pairs)
__global__ void gemm1_kernel(const float* __restrict__ x,
                             const float* __restrict__ Wl,
                             const float* __restrict__ Wr) {
    __shared__ float xs[32][128];
    int row0 = blockIdx.x * 32;
    float4* xsv = (float4*)&xs[0][0];
    for (int i = threadIdx.x; i < 32 * 32; i += 256) {
        int r = row0 + (i >> 5);
        float4 v = make_float4(0.f, 0.f, 0.f, 0.f);
        if (r < N_NODES) v = ((const float4*)x)[(size_t)r * 32 + (i & 31)];
        xsv[i] = v;
    }
    __syncthreads();

    int tx = threadIdx.x & 63;   // cols tx, tx+64 (Wl) ; tx, tx+64 (Wr)
    int ty = threadIdx.x >> 6;   // rows ty*8 .. ty*8+7

    unsigned long long acc[4][4];   // [col-slot][row-pair], packed (r_even, r_odd)
#pragma unroll
    for (int c = 0; c < 4; c++)
#pragma unroll
        for (int p = 0; p < 4; p++) acc[c][p] = 0ull;

#pragma unroll 2
    for (int k = 0; k < 128; k++) {
        unsigned long long wp[4];
        wp[0] = pack2(Wl[k * 128 + tx],      Wl[k * 128 + tx]);
        wp[1] = pack2(Wl[k * 128 + tx + 64], Wl[k * 128 + tx + 64]);
        wp[2] = pack2(Wr[k * 128 + tx],      Wr[k * 128 + tx]);
        wp[3] = pack2(Wr[k * 128 + tx + 64], Wr[k * 128 + tx + 64]);
#pragma unroll
        for (int p = 0; p < 4; p++) {
            unsigned long long xp = pack2(xs[ty * 8 + 2 * p][k], xs[ty * 8 + 2 * p + 1][k]);
#pragma unroll
            for (int c = 0; c < 4; c++) FMA2(acc[c][p], xp, wp[c]);
        }
    }

#pragma unroll
    for (int p = 0; p < 4; p++) {
#pragma unroll
        for (int c = 0; c < 4; c++) {
            float lo, hi;
            unpack2(acc[c][p], lo, hi);
            int r_lo = row0 + ty * 8 + 2 * p;
            int col = (c & 1) ? tx + 64 : tx;
            float* dstbuf = (c < 2) ? g_xl1 : g_xr1;
            if (r_lo < N_NODES)     dstbuf[(size_t)r_lo * 128 + col] = lo;
            if (r_lo + 1 < N_NODES) dstbuf[(size_t)(r_lo + 1) * 128 + col] = hi;
        }
    }
}

// ---------------- fused layer 1: warp per dst node --------------------------
// Single pass: accumulate denom = sum(ea), acc = sum(ea * xl[src]); then
// out = acc/denom + b1, ELU. Lanes 0-15 head 0 (ch 0..63), 16-31 head 1.
__global__ void fused_l1_kernel(const float* __restrict__ att1,
                                const float* __restrict__ b1) {
    int dst = (blockIdx.x * blockDim.x + threadIdx.x) >> 5;
    if (dst >= N_NODES) return;
    int lane = threadIdx.x & 31;
    int c0 = lane * 4;

    float4 b  = *(const float4*)(g_xr1 + (size_t)dst * 128 + c0);
    float4 at = *(const float4*)(att1 + c0);

    float4 acc = make_float4(0.f, 0.f, 0.f, 0.f);
    float denom = 0.f;

    int rs = g_rowptr[dst], re = g_rowptr[dst + 1];
    for (int i0 = rs; i0 < re; i0 += 32) {
        int n = re - i0; if (n > 32) n = 32;
        int sidx = (i0 + lane < re) ? g_csr_src[i0 + lane] : 0;
        for (int j = 0; j < n; j++) {
            int src = __shfl_sync(FULL, sidx, j);
            float4 a = *(const float4*)(g_xl1 + (size_t)src * 128 + c0);
            float p = at.x * lrelu(a.x + b.x) + at.y * lrelu(a.y + b.y)
                    + at.z * lrelu(a.z + b.z) + at.w * lrelu(a.w + b.w);
            p += __shfl_xor_sync(FULL, p, 8);
            p += __shfl_xor_sync(FULL, p, 4);
            p += __shfl_xor_sync(FULL, p, 2);
            p += __shfl_xor_sync(FULL, p, 1);
            float ea = __expf(p);     // alpha is provably small; no max pass
            denom += ea;
            acc.x += ea * a.x; acc.y += ea * a.y;
            acc.z += ea * a.z; acc.w += ea * a.w;
        }
    }
    float w = __fdividef(1.f, denom + 1e-16f);
    float4 bias = *(const float4*)(b1 + c0);
    float4 o;
    o.x = acc.x * w + bias.x; o.y = acc.y * w + bias.y;
    o.z = acc.z * w + bias.z; o.w = acc.w * w + bias.w;
    // ELU
    o.x = o.x > 0.f ? o.x : (__expf(o.x) - 1.f);
    o.y = o.y > 0.f ? o.y : (__expf(o.y) - 1.f);
    o.z = o.z > 0.f ? o.z : (__expf(o.z) - 1.f);
    o.w = o.w > 0.f ? o.w : (__expf(o.w) - 1.f);
    *(float4*)(g_h + (size_t)dst * 128 + c0) = o;
}

// ---------------- GEMM2: xl2 = h@W2l, xr2 = h@W2r  (K=128, N=3) -------------
__global__ void gemm2_kernel(const float* __restrict__ W2l,
                             const float* __restrict__ W2r) {
    int gid = blockIdx.x * blockDim.x + threadIdx.x;
    int row = gid >> 5;
    if (row >= N_NODES) return;
    int lane = threadIdx.x & 31;
    float4 hv = *(const float4*)(g_h + (size_t)row * 128 + lane * 4);
    float v[4] = {hv.x, hv.y, hv.z, hv.w};
    float pl[3] = {0.f, 0.f, 0.f};
    float pr[3] = {0.f, 0.f, 0.f};
#pragma unroll
    for (int j = 0; j < 4; j++) {
        int k = lane * 4 + j;
#pragma unroll
        for (int c = 0; c < 3; c++) {
            pl[c] += v[j] * W2l[k * 3 + c];
            pr[c] += v[j] * W2r[k * 3 + c];
        }
    }
#pragma unroll
    for (int o = 16; o >= 1; o >>= 1) {
#pragma unroll
        for (int c = 0; c < 3; c++) {
            pl[c] += __shfl_xor_sync(FULL, pl[c], o);
            pr[c] += __shfl_xor_sync(FULL, pr[c], o);
        }
    }
    if (lane == 0) {
#pragma unroll
        for (int c = 0; c < 3; c++) {
            g_xl2[row * 4 + c] = pl[c];
            g_xr2[row * 4 + c] = pr[c];
        }
    }
}

// ---------------- fused layer 2 + pool scatter: warp per dst ----------------
// heads=1, concat=false -> out[dst] = msg/denom + b2; scatter into graph pool.
__global__ void fused_l2_kernel(const float* __restrict__ att2,
                                const float* __restrict__ b2,
                                const int* __restrict__ batch) {
    int dst = (blockIdx.x * blockDim.x + threadIdx.x) >> 5;
    if (dst >= N_NODES) return;
    int lane = threadIdx.x & 31;
    float a0 = att2[0], a1 = att2[1], a2 = att2[2];
    float r0 = g_xr2[dst * 4 + 0], r1 = g_xr2[dst * 4 + 1], r2 = g_xr2[dst * 4 + 2];
    float d = 0.f, m0 = 0.f, m1 = 0.f, m2 = 0.f;
    int rs = g_rowptr[dst], re = g_rowptr[dst + 1];
    for (int i = rs + lane; i < re; i += 32) {
        int src = g_csr_src[i];
        float s0 = g_xl2[src * 4 + 0], s1 = g_xl2[src * 4 + 1], s2 = g_xl2[src * 4 + 2];
        float p = a0 * lrelu(s0 + r0) + a1 * lrelu(s1 + r1) + a2 * lrelu(s2 + r2);
        float ea = __expf(p);
        d += ea; m0 += ea * s0; m1 += ea * s1; m2 += ea * s2;
    }
#pragma unroll
    for (int o = 16; o >= 1; o >>= 1) {
        d  += __shfl_xor_sync(FULL, d, o);
        m0 += __shfl_xor_sync(FULL, m0, o);
        m1 += __shfl_xor_sync(FULL, m1, o);
        m2 += __shfl_xor_sync(FULL, m2, o);
    }
    if (lane == 0) {
        float w = __fdividef(1.f, d + 1e-16f);
        int g = batch[dst];
        atomicAdd(&g_pool[g * 4 + 0], m0 * w + b2[0]);
        atomicAdd(&g_pool[g * 4 + 1], m1 * w + b2[1]);
        atomicAdd(&g_pool[g * 4 + 2], m2 * w + b2[2]);
    }
}

// ---------------- final MLP: thread per graph -------------------------------
__global__ void mlp_kernel(const float* __restrict__ Wr1, const float* __restrict__ br1,
                           const float* __restrict__ Wr2, const float* __restrict__ br2,
                           float* __restrict__ out) {
    int g = threadIdx.x;
    if (g >= N_GRAPHS) return;
    float cnt = g_pool[g * 4 + 3];
    float inv = 1.f / fmaxf(cnt, 1.f);
    float v0 = g_pool[g * 4 + 0] * inv;
    float v1 = g_pool[g * 4 + 1] * inv;
    float v2 = g_pool[g * 4 + 2] * inv;
    float o0 = br2[0], o1 = br2[1], o2 = br2[2];
#pragma unroll 8
    for (int j = 0; j < 64; j++) {
        float hj = v0 * Wr1[j] + v1 * Wr1[64 + j] + v2 * Wr1[128 + j] + br1[j];
        hj = fmaxf(hj, 0.f);
        o0 += hj * Wr2[j * 3 + 0];
        o1 += hj * Wr2[j * 3 + 1];
        o2 += hj * Wr2[j * 3 + 2];
    }
    out[g * 3 + 0] = o0;
    out[g * 3 + 1] = o1;
    out[g * 3 + 2] = o2;
}

// ---------------- launch ----------------------------------------------------
extern "C" void kernel_launch(void* const* d_in, const int* in_sizes, int n_in,
                              void* d_out, int out_size) {
    (void)in_sizes; (void)n_in; (void)out_size;
    const float* x    = (const float*)d_in[0];
    const int*   ei   = (const int*)  d_in[1];
    const int*   batch= (const int*)  d_in[2];
    const float* W1l  = (const float*)d_in[3];
    const float* W1r  = (const float*)d_in[4];
    const float* att1 = (const float*)d_in[5];
    const float* b1   = (const float*)d_in[6];
    const float* W2l  = (const float*)d_in[7];
    const float* W2r  = (const float*)d_in[8];
    const float* att2 = (const float*)d_in[9];
    const float* b2   = (const float*)d_in[10];
    const float* Wr1  = (const float*)d_in[11];
    const float* br1  = (const float*)d_in[12];
    const float* Wr2  = (const float*)d_in[13];
    const float* br2  = (const float*)d_in[14];
    float* out = (float*)d_out;

    init_kernel<<<(N_NODES + 255) / 256, 256>>>();
    csr_count_kernel<<<(ET + 255) / 256, 256>>>(ei, batch);
    scan_kernel<<<1, 1024>>>();
    csr_fill_kernel<<<(ET + 255) / 256, 256>>>(ei);
    gemm1_kernel<<<(N_NODES + 31) / 32, 256>>>(x, W1l, W1r);
    {
        long long t = (long long)N_NODES * 32;
        fused_l1_kernel<<<(unsigned)((t + 255) / 256), 256>>>(att1, b1);
        gemm2_kernel<<<(unsigned)((t + 255) / 256), 256>>>(W2l, W2r);
        fused_l2_kernel<<<(unsigned)((t + 255) / 256), 256>>>(att2, b2, batch);
    }
    mlp_kernel<<<1, 64>>>(Wr1, br1, Wr2, br2, out);
}